// round 2
// baseline (speedup 1.0000x reference)
#include <cuda_runtime.h>

#define BB 16
#define CC 16
#define PP 512
#define DD 256

// Scratch (allocation-free rule: __device__ globals)
__device__ float g_ctx[BB*CC*PP*DD];   // 134 MB
__device__ float g_q  [BB*CC*PP*DD];   // 134 MB
__device__ float g_k  [BB*CC*PP*DD];   // 134 MB
__device__ float g_v  [BB*CC*PP*DD];   // 134 MB
__device__ float g_sc [BB*CC*PP*PP];   // 268 MB

// ---------------------------------------------------------------------------
// Kernel 1: context[b,c,p,d] = sum_c'(aw[c',p,d]*q[b,c',p,d]) - aw[c,p,d]*q[b,c,p,d]
// ---------------------------------------------------------------------------
__global__ void ctx_kernel(const float* __restrict__ query,
                           const float* __restrict__ aw) {
    int idx = blockIdx.x * blockDim.x + threadIdx.x;  // over B*P*D = 2,097,152
    if (idx >= BB*PP*DD) return;
    int d = idx % DD;
    int p = (idx / DD) % PP;
    int b = idx / (PP*DD);

    float vals[CC];
    float sum = 0.f;
#pragma unroll
    for (int c = 0; c < CC; c++) {
        float v = aw[(c*PP + p)*DD + d] * query[((b*CC + c)*PP + p)*DD + d];
        vals[c] = v;
        sum += v;
    }
#pragma unroll
    for (int c = 0; c < CC; c++) {
        g_ctx[((b*CC + c)*PP + p)*DD + d] = sum - vals[c];
    }
}

// ---------------------------------------------------------------------------
// Kernel 2: fused q/k/v projections: out = relu(X @ W + bias) [* 1/16 for q]
//   X: (P=512, D=256), W: (D, D) row-major, per (type, b, c)
//   blockIdx.z = type*(B*C) + b*C + c ; 64x64 tile, K-step 16, 4x4 micro-tile
// ---------------------------------------------------------------------------
__global__ void proj_kernel(const float* __restrict__ query,
                            const float* __restrict__ wq,
                            const float* __restrict__ wk,
                            const float* __restrict__ wv,
                            const float* __restrict__ bq,
                            const float* __restrict__ bk,
                            const float* __restrict__ bv) {
    __shared__ float As[16][68];
    __shared__ float Bs[16][68];

    int z    = blockIdx.z;
    int type = z / (BB*CC);
    int bc   = z % (BB*CC);
    int c    = bc % CC;

    const float* A    = (type == 0 ? query : (const float*)g_ctx) + bc * PP * DD;
    const float* W    = (type == 0 ? wq : (type == 1 ? wk : wv)) + c * DD * DD;
    const float* bias = (type == 0 ? bq : (type == 1 ? bk : bv)) + c * DD;
    float*       out  = (type == 0 ? g_q : (type == 1 ? g_k : g_v)) + bc * PP * DD;

    int m0 = blockIdx.y * 64;
    int n0 = blockIdx.x * 64;
    int t  = threadIdx.x;       // 256 threads
    int tx = t & 15, ty = t >> 4;

    int ka = t & 15, ma = t >> 4;   // A-tile load coords
    int nb = t & 63, kb = t >> 6;   // B-tile load coords

    float acc[4][4] = {};

    for (int k0 = 0; k0 < DD; k0 += 16) {
#pragma unroll
        for (int i = 0; i < 4; i++)
            As[ka][ma + 16*i] = A[(m0 + ma + 16*i)*DD + k0 + ka];
#pragma unroll
        for (int j = 0; j < 4; j++)
            Bs[kb + 4*j][nb] = W[(k0 + kb + 4*j)*DD + n0 + nb];
        __syncthreads();
#pragma unroll
        for (int kk = 0; kk < 16; kk++) {
            float4 a4 = *(const float4*)&As[kk][ty*4];
            float4 b4 = *(const float4*)&Bs[kk][tx*4];
            float a_[4] = {a4.x, a4.y, a4.z, a4.w};
            float b_[4] = {b4.x, b4.y, b4.z, b4.w};
#pragma unroll
            for (int i = 0; i < 4; i++)
#pragma unroll
                for (int j = 0; j < 4; j++)
                    acc[i][j] += a_[i] * b_[j];
        }
        __syncthreads();
    }

    float scale = (type == 0) ? 0.0625f : 1.0f;   // d^-0.5 folded into q
    float bb0 = bias[n0 + tx*4 + 0];
    float bb1 = bias[n0 + tx*4 + 1];
    float bb2 = bias[n0 + tx*4 + 2];
    float bb3 = bias[n0 + tx*4 + 3];
#pragma unroll
    for (int i = 0; i < 4; i++) {
        int row = m0 + ty*4 + i;
        float4 o;
        o.x = fmaxf(acc[i][0] + bb0, 0.f) * scale;
        o.y = fmaxf(acc[i][1] + bb1, 0.f) * scale;
        o.z = fmaxf(acc[i][2] + bb2, 0.f) * scale;
        o.w = fmaxf(acc[i][3] + bb3, 0.f) * scale;
        *(float4*)&out[row*DD + n0 + tx*4] = o;
    }
}

// ---------------------------------------------------------------------------
// Kernel 3: scores[p,q] = sum_e qhat[p,e] * khat[q,e]   (B transposed GEMM)
//   per (b,c): M=N=512, K=256
// ---------------------------------------------------------------------------
__global__ void scores_kernel() {
    __shared__ float As[16][68];
    __shared__ float Bs[16][68];

    int bc = blockIdx.z;
    const float* Q = g_q + bc * PP * DD;
    const float* K = g_k + bc * PP * DD;
    float*       S = g_sc + bc * PP * PP;

    int m0 = blockIdx.y * 64;
    int n0 = blockIdx.x * 64;
    int t  = threadIdx.x;
    int tx = t & 15, ty = t >> 4;

    int ka = t & 15, ma = t >> 4;
    int kb = t & 15, nb = t >> 4;   // transposed B load

    float acc[4][4] = {};

    for (int k0 = 0; k0 < DD; k0 += 16) {
#pragma unroll
        for (int i = 0; i < 4; i++)
            As[ka][ma + 16*i] = Q[(m0 + ma + 16*i)*DD + k0 + ka];
#pragma unroll
        for (int j = 0; j < 4; j++)
            Bs[kb][nb + 16*j] = K[(n0 + nb + 16*j)*DD + k0 + kb];
        __syncthreads();
#pragma unroll
        for (int kk = 0; kk < 16; kk++) {
            float4 a4 = *(const float4*)&As[kk][ty*4];
            float4 b4 = *(const float4*)&Bs[kk][tx*4];
            float a_[4] = {a4.x, a4.y, a4.z, a4.w};
            float b_[4] = {b4.x, b4.y, b4.z, b4.w};
#pragma unroll
            for (int i = 0; i < 4; i++)
#pragma unroll
                for (int j = 0; j < 4; j++)
                    acc[i][j] += a_[i] * b_[j];
        }
        __syncthreads();
    }

#pragma unroll
    for (int i = 0; i < 4; i++) {
        int row = m0 + ty*4 + i;
        float4 o = {acc[i][0], acc[i][1], acc[i][2], acc[i][3]};
        *(float4*)&S[row*PP + n0 + tx*4] = o;
    }
}

// ---------------------------------------------------------------------------
// Kernel 4: row softmax over the last dim (512). One block per row.
// ---------------------------------------------------------------------------
__global__ void softmax_kernel() {
    __shared__ float red[8];
    int row = blockIdx.x;                 // over B*C*P = 131072
    float* r = g_sc + (size_t)row * PP;
    int t = threadIdx.x;                  // 256 threads, 2 elems each

    float2 v = *(float2*)(r + 2*t);
    float m = fmaxf(v.x, v.y);
#pragma unroll
    for (int o = 16; o; o >>= 1) m = fmaxf(m, __shfl_xor_sync(0xffffffffu, m, o));
    if ((t & 31) == 0) red[t >> 5] = m;
    __syncthreads();
    m = red[0];
#pragma unroll
    for (int i = 1; i < 8; i++) m = fmaxf(m, red[i]);
    __syncthreads();

    float e0 = __expf(v.x - m);
    float e1 = __expf(v.y - m);
    float s = e0 + e1;
#pragma unroll
    for (int o = 16; o; o >>= 1) s += __shfl_xor_sync(0xffffffffu, s, o);
    if ((t & 31) == 0) red[t >> 5] = s;
    __syncthreads();
    s = red[0];
#pragma unroll
    for (int i = 1; i < 8; i++) s += red[i];

    float inv = 1.f / s;
    float2 o2 = {e0 * inv, e1 * inv};
    *(float2*)(r + 2*t) = o2;
}

// ---------------------------------------------------------------------------
// Kernel 5: out = attn @ v : per (b,c) M=512, K=512, N=256
// ---------------------------------------------------------------------------
__global__ void av_kernel(float* __restrict__ out) {
    __shared__ float As[16][68];
    __shared__ float Bs[16][68];

    int bc = blockIdx.z;
    const float* A = g_sc + (size_t)bc * PP * PP;   // ld = 512
    const float* V = g_v  + bc * PP * DD;           // ld = 256
    float*       O = out  + bc * PP * DD;

    int m0 = blockIdx.y * 64;
    int n0 = blockIdx.x * 64;
    int t  = threadIdx.x;
    int tx = t & 15, ty = t >> 4;

    int ka = t & 15, ma = t >> 4;
    int nb = t & 63, kb = t >> 6;

    float acc[4][4] = {};

    for (int k0 = 0; k0 < PP; k0 += 16) {
#pragma unroll
        for (int i = 0; i < 4; i++)
            As[ka][ma + 16*i] = A[(m0 + ma + 16*i)*PP + k0 + ka];
#pragma unroll
        for (int j = 0; j < 4; j++)
            Bs[kb + 4*j][nb] = V[(k0 + kb + 4*j)*DD + n0 + nb];
        __syncthreads();
#pragma unroll
        for (int kk = 0; kk < 16; kk++) {
            float4 a4 = *(const float4*)&As[kk][ty*4];
            float4 b4 = *(const float4*)&Bs[kk][tx*4];
            float a_[4] = {a4.x, a4.y, a4.z, a4.w};
            float b_[4] = {b4.x, b4.y, b4.z, b4.w};
#pragma unroll
            for (int i = 0; i < 4; i++)
#pragma unroll
                for (int j = 0; j < 4; j++)
                    acc[i][j] += a_[i] * b_[j];
        }
        __syncthreads();
    }

#pragma unroll
    for (int i = 0; i < 4; i++) {
        int row = m0 + ty*4 + i;
        float4 o = {acc[i][0], acc[i][1], acc[i][2], acc[i][3]};
        *(float4*)&O[row*DD + n0 + tx*4] = o;
    }
}

// ---------------------------------------------------------------------------
extern "C" void kernel_launch(void* const* d_in, const int* in_sizes, int n_in,
                              void* d_out, int out_size) {
    (void)in_sizes; (void)n_in; (void)out_size;
    const float* query = (const float*)d_in[0];
    const float* aw    = (const float*)d_in[1];
    const float* wq    = (const float*)d_in[2];
    const float* wk    = (const float*)d_in[3];
    const float* wv    = (const float*)d_in[4];
    const float* bq    = (const float*)d_in[5];
    const float* bk    = (const float*)d_in[6];
    const float* bv    = (const float*)d_in[7];
    float* out = (float*)d_out;

    int n_ctx = BB*PP*DD;
    ctx_kernel<<<(n_ctx + 255)/256, 256>>>(query, aw);
    proj_kernel<<<dim3(DD/64, PP/64, 3*BB*CC), 256>>>(query, wq, wk, wv, bq, bk, bv);
    scores_kernel<<<dim3(PP/64, PP/64, BB*CC), 256>>>();
    softmax_kernel<<<BB*CC*PP, 256>>>();
    av_kernel<<<dim3(DD/64, PP/64, BB*CC), 256>>>(out);
}

// round 3
// speedup vs baseline: 1.9375x; 1.9375x over previous
#include <cuda_runtime.h>
#include <cstdint>

#define BB 16
#define CC 16
#define PP 512
#define DD 256

// Scratch (allocation-free rule: __device__ globals)
__device__ float g_ctx[BB*CC*PP*DD];   // 134 MB
__device__ float g_q  [BB*CC*PP*DD];   // 134 MB
__device__ float g_k  [BB*CC*PP*DD];   // 134 MB
__device__ float g_v  [BB*CC*PP*DD];   // 134 MB
__device__ float g_sc [BB*CC*PP*PP];   // 268 MB

// ---------------------------------------------------------------------------
// helpers
// ---------------------------------------------------------------------------
__device__ __forceinline__ uint32_t cvt_tf32(float x) {
    uint32_t u;
    asm("cvt.rna.tf32.f32 %0, %1;" : "=r"(u) : "f"(x));
    return u;
}

__device__ __forceinline__ void mma8(float* c, const uint32_t* a, const uint32_t* b) {
    asm volatile(
        "mma.sync.aligned.m16n8k8.row.col.f32.tf32.tf32.f32 "
        "{%0,%1,%2,%3}, {%4,%5,%6,%7}, {%8,%9}, {%0,%1,%2,%3};"
        : "+f"(c[0]), "+f"(c[1]), "+f"(c[2]), "+f"(c[3])
        : "r"(a[0]), "r"(a[1]), "r"(a[2]), "r"(a[3]),
          "r"(b[0]), "r"(b[1]));
}

// ---------------------------------------------------------------------------
// Kernel 1: context[b,c,p,d] = sum_c'(aw*q) - aw[c]*q[c]
// ---------------------------------------------------------------------------
__global__ void ctx_kernel(const float* __restrict__ query,
                           const float* __restrict__ aw) {
    int idx = blockIdx.x * blockDim.x + threadIdx.x;  // over B*P*D
    if (idx >= BB*PP*DD) return;
    int d = idx % DD;
    int p = (idx / DD) % PP;
    int b = idx / (PP*DD);

    float vals[CC];
    float sum = 0.f;
#pragma unroll
    for (int c = 0; c < CC; c++) {
        float v = aw[(c*PP + p)*DD + d] * query[((b*CC + c)*PP + p)*DD + d];
        vals[c] = v;
        sum += v;
    }
#pragma unroll
    for (int c = 0; c < CC; c++) {
        g_ctx[((b*CC + c)*PP + p)*DD + d] = sum - vals[c];
    }
}

// ---------------------------------------------------------------------------
// Kernel 2 (tensor): fused q/k/v projections. out = relu(X@W + bias) [*1/16 q]
//   Block tile 128(M)x128(N), Kc=32. 8 warps, each 64x32.
//   A: [m][k] smem stride 36 (conflict-free frags). B (W is k-major): [k][n] stride 136.
// ---------------------------------------------------------------------------
__global__ void __launch_bounds__(256) proj_tc(const float* __restrict__ query,
                            const float* __restrict__ wq,
                            const float* __restrict__ wk,
                            const float* __restrict__ wv,
                            const float* __restrict__ bq,
                            const float* __restrict__ bk,
                            const float* __restrict__ bv) {
    __shared__ uint32_t As[128][36];
    __shared__ uint32_t Bs[32][136];

    int z    = blockIdx.z;
    int type = z / (BB*CC);
    int bc   = z % (BB*CC);
    int c    = bc % CC;

    const float* A    = (type == 0 ? query : (const float*)g_ctx) + bc * PP * DD;
    const float* W    = (type == 0 ? wq : (type == 1 ? wk : wv)) + c * DD * DD;
    const float* bias = (type == 0 ? bq : (type == 1 ? bk : bv)) + c * DD;
    float*       out  = (type == 0 ? g_q : (type == 1 ? g_k : g_v)) + bc * PP * DD;

    int m0 = blockIdx.y * 128;
    int n0 = blockIdx.x * 128;
    int t  = threadIdx.x;
    int lane = t & 31, wid = t >> 5;
    int wm = wid >> 2, wn = wid & 3;   // warp 64x32 tile
    int g = lane >> 2, tg = lane & 3;

    float acc[4][4][4] = {};

    for (int k0 = 0; k0 < DD; k0 += 32) {
#pragma unroll
        for (int i = 0; i < 4; i++) {
            int idx = t + i*256;
            int row = idx >> 3, q = idx & 7;
            float4 v = *(const float4*)&A[(m0+row)*DD + k0 + q*4];
            uint32_t* dst = &As[row][q*4];
            dst[0]=cvt_tf32(v.x); dst[1]=cvt_tf32(v.y); dst[2]=cvt_tf32(v.z); dst[3]=cvt_tf32(v.w);
        }
#pragma unroll
        for (int i = 0; i < 4; i++) {
            int idx = t + i*256;
            int kr = idx >> 5, q = idx & 31;
            float4 v = *(const float4*)&W[(k0+kr)*DD + n0 + q*4];
            uint32_t* dst = &Bs[kr][q*4];
            dst[0]=cvt_tf32(v.x); dst[1]=cvt_tf32(v.y); dst[2]=cvt_tf32(v.z); dst[3]=cvt_tf32(v.w);
        }
        __syncthreads();
#pragma unroll
        for (int kt = 0; kt < 32; kt += 8) {
            uint32_t af[4][4], bf[4][2];
#pragma unroll
            for (int mt = 0; mt < 4; mt++) {
                int r = wm*64 + mt*16;
                af[mt][0] = As[r+g   ][kt+tg];
                af[mt][1] = As[r+g+8 ][kt+tg];
                af[mt][2] = As[r+g   ][kt+tg+4];
                af[mt][3] = As[r+g+8 ][kt+tg+4];
            }
#pragma unroll
            for (int nt = 0; nt < 4; nt++) {
                int cc2 = wn*32 + nt*8 + g;
                bf[nt][0] = Bs[kt+tg  ][cc2];
                bf[nt][1] = Bs[kt+tg+4][cc2];
            }
#pragma unroll
            for (int mt = 0; mt < 4; mt++)
#pragma unroll
                for (int nt = 0; nt < 4; nt++)
                    mma8(acc[mt][nt], af[mt], bf[nt]);
        }
        __syncthreads();
    }

    float scale = (type == 0) ? 0.0625f : 1.0f;
#pragma unroll
    for (int mt = 0; mt < 4; mt++) {
#pragma unroll
        for (int nt = 0; nt < 4; nt++) {
            int row = m0 + wm*64 + mt*16 + g;
            int col = n0 + wn*32 + nt*8 + 2*tg;
            float b0v = bias[col], b1v = bias[col+1];
            float* o = acc[mt][nt];
            out[row*DD + col]       = fmaxf(o[0] + b0v, 0.f) * scale;
            out[row*DD + col + 1]   = fmaxf(o[1] + b1v, 0.f) * scale;
            out[(row+8)*DD + col]   = fmaxf(o[2] + b0v, 0.f) * scale;
            out[(row+8)*DD + col+1] = fmaxf(o[3] + b1v, 0.f) * scale;
        }
    }
}

// ---------------------------------------------------------------------------
// Kernel 3 (tensor): scores = q @ k^T. per (b,c): M=N=512, K=256.
//   B (g_k) is n-major [n][k] in global -> Bs[n][k] stride 36, no transpose.
// ---------------------------------------------------------------------------
__global__ void __launch_bounds__(256) scores_tc() {
    __shared__ uint32_t As[128][36];
    __shared__ uint32_t Bs[128][36];

    int bc = blockIdx.z;
    const float* Q = g_q + bc * PP * DD;
    const float* K = g_k + bc * PP * DD;
    float*       S = g_sc + (size_t)bc * PP * PP;

    int m0 = blockIdx.y * 128;
    int n0 = blockIdx.x * 128;
    int t  = threadIdx.x;
    int lane = t & 31, wid = t >> 5;
    int wm = wid >> 2, wn = wid & 3;
    int g = lane >> 2, tg = lane & 3;

    float acc[4][4][4] = {};

    for (int k0 = 0; k0 < DD; k0 += 32) {
#pragma unroll
        for (int i = 0; i < 4; i++) {
            int idx = t + i*256;
            int row = idx >> 3, q = idx & 7;
            float4 v = *(const float4*)&Q[(m0+row)*DD + k0 + q*4];
            uint32_t* dst = &As[row][q*4];
            dst[0]=cvt_tf32(v.x); dst[1]=cvt_tf32(v.y); dst[2]=cvt_tf32(v.z); dst[3]=cvt_tf32(v.w);
        }
#pragma unroll
        for (int i = 0; i < 4; i++) {
            int idx = t + i*256;
            int row = idx >> 3, q = idx & 7;
            float4 v = *(const float4*)&K[(n0+row)*DD + k0 + q*4];
            uint32_t* dst = &Bs[row][q*4];
            dst[0]=cvt_tf32(v.x); dst[1]=cvt_tf32(v.y); dst[2]=cvt_tf32(v.z); dst[3]=cvt_tf32(v.w);
        }
        __syncthreads();
#pragma unroll
        for (int kt = 0; kt < 32; kt += 8) {
            uint32_t af[4][4], bf[4][2];
#pragma unroll
            for (int mt = 0; mt < 4; mt++) {
                int r = wm*64 + mt*16;
                af[mt][0] = As[r+g   ][kt+tg];
                af[mt][1] = As[r+g+8 ][kt+tg];
                af[mt][2] = As[r+g   ][kt+tg+4];
                af[mt][3] = As[r+g+8 ][kt+tg+4];
            }
#pragma unroll
            for (int nt = 0; nt < 4; nt++) {
                int nr = wn*32 + nt*8 + g;
                bf[nt][0] = Bs[nr][kt+tg];
                bf[nt][1] = Bs[nr][kt+tg+4];
            }
#pragma unroll
            for (int mt = 0; mt < 4; mt++)
#pragma unroll
                for (int nt = 0; nt < 4; nt++)
                    mma8(acc[mt][nt], af[mt], bf[nt]);
        }
        __syncthreads();
    }

#pragma unroll
    for (int mt = 0; mt < 4; mt++) {
#pragma unroll
        for (int nt = 0; nt < 4; nt++) {
            int row = m0 + wm*64 + mt*16 + g;
            int col = n0 + wn*32 + nt*8 + 2*tg;
            float* o = acc[mt][nt];
            S[(size_t)row*PP + col]       = o[0];
            S[(size_t)row*PP + col + 1]   = o[1];
            S[(size_t)(row+8)*PP + col]   = o[2];
            S[(size_t)(row+8)*PP + col+1] = o[3];
        }
    }
}

// ---------------------------------------------------------------------------
// Kernel 4: row softmax over the last dim (512). One block per row.
// ---------------------------------------------------------------------------
__global__ void softmax_kernel() {
    __shared__ float red[8];
    int row = blockIdx.x;                 // over B*C*P
    float* r = g_sc + (size_t)row * PP;
    int t = threadIdx.x;                  // 256 threads, 2 elems each

    float2 v = *(float2*)(r + 2*t);
    float m = fmaxf(v.x, v.y);
#pragma unroll
    for (int o = 16; o; o >>= 1) m = fmaxf(m, __shfl_xor_sync(0xffffffffu, m, o));
    if ((t & 31) == 0) red[t >> 5] = m;
    __syncthreads();
    m = red[0];
#pragma unroll
    for (int i = 1; i < 8; i++) m = fmaxf(m, red[i]);
    __syncthreads();

    float e0 = __expf(v.x - m);
    float e1 = __expf(v.y - m);
    float s = e0 + e1;
#pragma unroll
    for (int o = 16; o; o >>= 1) s += __shfl_xor_sync(0xffffffffu, s, o);
    if ((t & 31) == 0) red[t >> 5] = s;
    __syncthreads();
    s = red[0];
#pragma unroll
    for (int i = 1; i < 8; i++) s += red[i];

    float inv = 1.f / s;
    float2 o2 = {e0 * inv, e1 * inv};
    *(float2*)(r + 2*t) = o2;
}

// ---------------------------------------------------------------------------
// Kernel 5 (tensor): out = attn @ v. per (b,c): M=512, K=512, N=256.
//   A = g_sc (ld 512), B = g_v k-major -> Bs[k][n] stride 136.
// ---------------------------------------------------------------------------
__global__ void __launch_bounds__(256) av_tc(float* __restrict__ out) {
    __shared__ uint32_t As[128][36];
    __shared__ uint32_t Bs[32][136];

    int bc = blockIdx.z;
    const float* A = g_sc + (size_t)bc * PP * PP;   // ld = 512
    const float* V = g_v  + bc * PP * DD;           // ld = 256
    float*       O = out  + bc * PP * DD;

    int m0 = blockIdx.y * 128;
    int n0 = blockIdx.x * 128;
    int t  = threadIdx.x;
    int lane = t & 31, wid = t >> 5;
    int wm = wid >> 2, wn = wid & 3;
    int g = lane >> 2, tg = lane & 3;

    float acc[4][4][4] = {};

    for (int k0 = 0; k0 < PP; k0 += 32) {
#pragma unroll
        for (int i = 0; i < 4; i++) {
            int idx = t + i*256;
            int row = idx >> 3, q = idx & 7;
            float4 v = *(const float4*)&A[(size_t)(m0+row)*PP + k0 + q*4];
            uint32_t* dst = &As[row][q*4];
            dst[0]=cvt_tf32(v.x); dst[1]=cvt_tf32(v.y); dst[2]=cvt_tf32(v.z); dst[3]=cvt_tf32(v.w);
        }
#pragma unroll
        for (int i = 0; i < 4; i++) {
            int idx = t + i*256;
            int kr = idx >> 5, q = idx & 31;
            float4 v = *(const float4*)&V[(k0+kr)*DD + n0 + q*4];
            uint32_t* dst = &Bs[kr][q*4];
            dst[0]=cvt_tf32(v.x); dst[1]=cvt_tf32(v.y); dst[2]=cvt_tf32(v.z); dst[3]=cvt_tf32(v.w);
        }
        __syncthreads();
#pragma unroll
        for (int kt = 0; kt < 32; kt += 8) {
            uint32_t af[4][4], bf[4][2];
#pragma unroll
            for (int mt = 0; mt < 4; mt++) {
                int r = wm*64 + mt*16;
                af[mt][0] = As[r+g   ][kt+tg];
                af[mt][1] = As[r+g+8 ][kt+tg];
                af[mt][2] = As[r+g   ][kt+tg+4];
                af[mt][3] = As[r+g+8 ][kt+tg+4];
            }
#pragma unroll
            for (int nt = 0; nt < 4; nt++) {
                int cc2 = wn*32 + nt*8 + g;
                bf[nt][0] = Bs[kt+tg  ][cc2];
                bf[nt][1] = Bs[kt+tg+4][cc2];
            }
#pragma unroll
            for (int mt = 0; mt < 4; mt++)
#pragma unroll
                for (int nt = 0; nt < 4; nt++)
                    mma8(acc[mt][nt], af[mt], bf[nt]);
        }
        __syncthreads();
    }

#pragma unroll
    for (int mt = 0; mt < 4; mt++) {
#pragma unroll
        for (int nt = 0; nt < 4; nt++) {
            int row = m0 + wm*64 + mt*16 + g;
            int col = n0 + wn*32 + nt*8 + 2*tg;
            float* o = acc[mt][nt];
            O[row*DD + col]       = o[0];
            O[row*DD + col + 1]   = o[1];
            O[(row+8)*DD + col]   = o[2];
            O[(row+8)*DD + col+1] = o[3];
        }
    }
}

// ---------------------------------------------------------------------------
extern "C" void kernel_launch(void* const* d_in, const int* in_sizes, int n_in,
                              void* d_out, int out_size) {
    (void)in_sizes; (void)n_in; (void)out_size;
    const float* query = (const float*)d_in[0];
    const float* aw    = (const float*)d_in[1];
    const float* wq    = (const float*)d_in[2];
    const float* wk    = (const float*)d_in[3];
    const float* wv    = (const float*)d_in[4];
    const float* bq    = (const float*)d_in[5];
    const float* bk    = (const float*)d_in[6];
    const float* bv    = (const float*)d_in[7];
    float* out = (float*)d_out;

    int n_ctx = BB*PP*DD;
    ctx_kernel<<<(n_ctx + 255)/256, 256>>>(query, aw);
    proj_tc<<<dim3(DD/128, PP/128, 3*BB*CC), 256>>>(query, wq, wk, wv, bq, bk, bv);
    scores_tc<<<dim3(PP/128, PP/128, BB*CC), 256>>>();
    softmax_kernel<<<BB*CC*PP, 256>>>();
    av_tc<<<dim3(DD/128, PP/128, BB*CC), 256>>>(out);
}

// round 9
// speedup vs baseline: 3.6099x; 1.8632x over previous
#include <cuda_runtime.h>
#include <cstdint>

#define BB 16
#define CC 16
#define PP 512
#define DD 256

// Scratch (allocation-free rule: __device__ globals)
__device__ float g_ctx[BB*CC*PP*DD];   // 134 MB
__device__ float g_q  [BB*CC*PP*DD];   // 134 MB
__device__ float g_k  [BB*CC*PP*DD];   // 134 MB
__device__ float g_v  [BB*CC*PP*DD];   // 134 MB
__device__ float g_sc [BB*CC*PP*PP];   // 268 MB

// ---------------------------------------------------------------------------
// helpers
// ---------------------------------------------------------------------------
__device__ __forceinline__ uint32_t f2tf(float x) {
    uint32_t u;
    asm("cvt.rna.tf32.f32 %0, %1;" : "=r"(u) : "f"(x));
    return u;
}

__device__ __forceinline__ void mma8(float* c, const uint32_t* a, const uint32_t* b) {
    asm volatile(
        "mma.sync.aligned.m16n8k8.row.col.f32.tf32.tf32.f32 "
        "{%0,%1,%2,%3}, {%4,%5,%6,%7}, {%8,%9}, {%0,%1,%2,%3};"
        : "+f"(c[0]), "+f"(c[1]), "+f"(c[2]), "+f"(c[3])
        : "r"(a[0]), "r"(a[1]), "r"(a[2]), "r"(a[3]),
          "r"(b[0]), "r"(b[1]));
}

__device__ __forceinline__ void cpa16(uint32_t dst, const void* src) {
    asm volatile("cp.async.cg.shared.global [%0], [%1], 16;" :: "r"(dst), "l"(src));
}
#define CP_COMMIT() asm volatile("cp.async.commit_group;")
#define CP_WAIT0()  asm volatile("cp.async.wait_group 0;")
#define CP_WAIT1()  asm volatile("cp.async.wait_group 1;")

__device__ __forceinline__ uint32_t s2u(const void* p) {
    return (uint32_t)__cvta_generic_to_shared(p);
}

// ---------------------------------------------------------------------------
// Kernel 1: context[b,c,p,d] = sum_c'(aw*q) - aw[c]*q[c]
// ---------------------------------------------------------------------------
__global__ void ctx_kernel(const float* __restrict__ query,
                           const float* __restrict__ aw) {
    int idx = blockIdx.x * blockDim.x + threadIdx.x;  // over B*P*D
    if (idx >= BB*PP*DD) return;
    int d = idx % DD;
    int p = (idx / DD) % PP;
    int b = idx / (PP*DD);

    float vals[CC];
    float sum = 0.f;
#pragma unroll
    for (int c = 0; c < CC; c++) {
        float v = aw[(c*PP + p)*DD + d] * query[((b*CC + c)*PP + p)*DD + d];
        vals[c] = v;
        sum += v;
    }
#pragma unroll
    for (int c = 0; c < CC; c++) {
        g_ctx[((b*CC + c)*PP + p)*DD + d] = sum - vals[c];
    }
}

// ---------------------------------------------------------------------------
// Kernel 2 (tensor, cp.async pipelined): fused q/k/v projections.
//   out = relu(X@W + bias) [*1/16 for q]. 128x128 tile, Kc=32, 8 warps 64x32.
//   As[2][128][36] (m-major), Bs[2][32][136] (k-major). cvt.rna at frag load.
// ---------------------------------------------------------------------------
__global__ void __launch_bounds__(256, 2) proj_tc(const float* __restrict__ query,
                            const float* __restrict__ wq,
                            const float* __restrict__ wk,
                            const float* __restrict__ wv,
                            const float* __restrict__ bq,
                            const float* __restrict__ bk,
                            const float* __restrict__ bv) {
    extern __shared__ float smem[];
    float (*As)[128][36]  = (float (*)[128][36])smem;
    float (*Bs)[32][136]  = (float (*)[32][136])(smem + 2*128*36);

    int z    = blockIdx.z;
    int type = z / (BB*CC);
    int bc   = z % (BB*CC);
    int c    = bc % CC;

    const float* A    = (type == 0 ? query : (const float*)g_ctx) + bc * PP * DD;
    const float* W    = (type == 0 ? wq : (type == 1 ? wk : wv)) + c * DD * DD;
    const float* bias = (type == 0 ? bq : (type == 1 ? bk : bv)) + c * DD;
    float*       out  = (type == 0 ? g_q : (type == 1 ? g_k : g_v)) + bc * PP * DD;

    int m0 = blockIdx.y * 128;
    int n0 = blockIdx.x * 128;
    int t  = threadIdx.x;
    int lane = t & 31, wid = t >> 5;
    int wm = wid >> 2, wn = wid & 3;   // warp 64x32 tile
    int g = lane >> 2, tg = lane & 3;

    int arow = t >> 3, aq = (t & 7) * 4;     // A: 128 rows x 32 cols
    int brow = t >> 5, bq4 = (t & 31) * 4;   // B: 32 rows x 128 cols

    float acc[4][4][4] = {};

    // prologue: chunk 0 -> buf 0
    {
        const int k0 = 0;
#pragma unroll
        for (int i = 0; i < 4; i++)
            cpa16(s2u(&As[0][arow + 32*i][aq]), &A[(m0 + arow + 32*i)*DD + k0 + aq]);
#pragma unroll
        for (int i = 0; i < 4; i++)
            cpa16(s2u(&Bs[0][brow + 8*i][bq4]), &W[(k0 + brow + 8*i)*DD + n0 + bq4]);
        CP_COMMIT();
    }

    const int NCH = DD / 32;  // 8
    for (int ch = 0; ch < NCH; ch++) {
        if (ch + 1 < NCH) {
            const int k0 = (ch + 1) * 32;
            int nb = (ch + 1) & 1;
#pragma unroll
            for (int i = 0; i < 4; i++)
                cpa16(s2u(&As[nb][arow + 32*i][aq]), &A[(m0 + arow + 32*i)*DD + k0 + aq]);
#pragma unroll
            for (int i = 0; i < 4; i++)
                cpa16(s2u(&Bs[nb][brow + 8*i][bq4]), &W[(k0 + brow + 8*i)*DD + n0 + bq4]);
            CP_COMMIT();
            CP_WAIT1();
        } else {
            CP_WAIT0();
        }
        __syncthreads();

        int cur = ch & 1;
        const float (*Ab)[36]  = As[cur];
        const float (*Bb)[136] = Bs[cur];
#pragma unroll
        for (int kt = 0; kt < 32; kt += 8) {
            uint32_t af[4][4], bf[4][2];
#pragma unroll
            for (int mt = 0; mt < 4; mt++) {
                int r = wm*64 + mt*16;
                af[mt][0] = f2tf(Ab[r+g   ][kt+tg]);
                af[mt][1] = f2tf(Ab[r+g+8 ][kt+tg]);
                af[mt][2] = f2tf(Ab[r+g   ][kt+tg+4]);
                af[mt][3] = f2tf(Ab[r+g+8 ][kt+tg+4]);
            }
#pragma unroll
            for (int nt = 0; nt < 4; nt++) {
                int cc2 = wn*32 + nt*8 + g;
                bf[nt][0] = f2tf(Bb[kt+tg  ][cc2]);
                bf[nt][1] = f2tf(Bb[kt+tg+4][cc2]);
            }
#pragma unroll
            for (int mt = 0; mt < 4; mt++)
#pragma unroll
                for (int nt = 0; nt < 4; nt++)
                    mma8(acc[mt][nt], af[mt], bf[nt]);
        }
        __syncthreads();
    }

    float scale = (type == 0) ? 0.0625f : 1.0f;
#pragma unroll
    for (int mt = 0; mt < 4; mt++) {
#pragma unroll
        for (int nt = 0; nt < 4; nt++) {
            int row = m0 + wm*64 + mt*16 + g;
            int col = n0 + wn*32 + nt*8 + 2*tg;
            float b0v = bias[col], b1v = bias[col+1];
            float* o = acc[mt][nt];
            float2 o0 = {fmaxf(o[0] + b0v, 0.f) * scale, fmaxf(o[1] + b1v, 0.f) * scale};
            float2 o1 = {fmaxf(o[2] + b0v, 0.f) * scale, fmaxf(o[3] + b1v, 0.f) * scale};
            *(float2*)&out[row*DD + col]     = o0;
            *(float2*)&out[(row+8)*DD + col] = o1;
        }
    }
}

// ---------------------------------------------------------------------------
// Kernel 3 (tensor, cp.async pipelined): scores = q @ k^T. M=N=512, K=256.
// ---------------------------------------------------------------------------
__global__ void __launch_bounds__(256, 2) scores_tc() {
    extern __shared__ float smem[];
    float (*As)[128][36] = (float (*)[128][36])smem;
    float (*Bs)[128][36] = (float (*)[128][36])(smem + 2*128*36);

    int bc = blockIdx.z;
    const float* Q = g_q + bc * PP * DD;
    const float* K = g_k + bc * PP * DD;
    float*       S = g_sc + (size_t)bc * PP * PP;

    int m0 = blockIdx.y * 128;
    int n0 = blockIdx.x * 128;
    int t  = threadIdx.x;
    int lane = t & 31, wid = t >> 5;
    int wm = wid >> 2, wn = wid & 3;
    int g = lane >> 2, tg = lane & 3;

    int arow = t >> 3, aq = (t & 7) * 4;

    float acc[4][4][4] = {};

    {
        const int k0 = 0;
#pragma unroll
        for (int i = 0; i < 4; i++)
            cpa16(s2u(&As[0][arow + 32*i][aq]), &Q[(m0 + arow + 32*i)*DD + k0 + aq]);
#pragma unroll
        for (int i = 0; i < 4; i++)
            cpa16(s2u(&Bs[0][arow + 32*i][aq]), &K[(n0 + arow + 32*i)*DD + k0 + aq]);
        CP_COMMIT();
    }

    const int NCH = DD / 32;  // 8
    for (int ch = 0; ch < NCH; ch++) {
        if (ch + 1 < NCH) {
            const int k0 = (ch + 1) * 32;
            int nb = (ch + 1) & 1;
#pragma unroll
            for (int i = 0; i < 4; i++)
                cpa16(s2u(&As[nb][arow + 32*i][aq]), &Q[(m0 + arow + 32*i)*DD + k0 + aq]);
#pragma unroll
            for (int i = 0; i < 4; i++)
                cpa16(s2u(&Bs[nb][arow + 32*i][aq]), &K[(n0 + arow + 32*i)*DD + k0 + aq]);
            CP_COMMIT();
            CP_WAIT1();
        } else {
            CP_WAIT0();
        }
        __syncthreads();

        int cur = ch & 1;
        const float (*Ab)[36] = As[cur];
        const float (*Bb)[36] = Bs[cur];
#pragma unroll
        for (int kt = 0; kt < 32; kt += 8) {
            uint32_t af[4][4], bf[4][2];
#pragma unroll
            for (int mt = 0; mt < 4; mt++) {
                int r = wm*64 + mt*16;
                af[mt][0] = f2tf(Ab[r+g   ][kt+tg]);
                af[mt][1] = f2tf(Ab[r+g+8 ][kt+tg]);
                af[mt][2] = f2tf(Ab[r+g   ][kt+tg+4]);
                af[mt][3] = f2tf(Ab[r+g+8 ][kt+tg+4]);
            }
#pragma unroll
            for (int nt = 0; nt < 4; nt++) {
                int nr = wn*32 + nt*8 + g;
                bf[nt][0] = f2tf(Bb[nr][kt+tg]);
                bf[nt][1] = f2tf(Bb[nr][kt+tg+4]);
            }
#pragma unroll
            for (int mt = 0; mt < 4; mt++)
#pragma unroll
                for (int nt = 0; nt < 4; nt++)
                    mma8(acc[mt][nt], af[mt], bf[nt]);
        }
        __syncthreads();
    }

#pragma unroll
    for (int mt = 0; mt < 4; mt++) {
#pragma unroll
        for (int nt = 0; nt < 4; nt++) {
            int row = m0 + wm*64 + mt*16 + g;
            int col = n0 + wn*32 + nt*8 + 2*tg;
            float* o = acc[mt][nt];
            *(float2*)&S[(size_t)row*PP + col]     = make_float2(o[0], o[1]);
            *(float2*)&S[(size_t)(row+8)*PP + col] = make_float2(o[2], o[3]);
        }
    }
}

// ---------------------------------------------------------------------------
// Kernel 4: softmax, one warp per 512-float row. 8 warps/block, no barriers.
// ---------------------------------------------------------------------------
__global__ void softmax_warp() {
    int row  = blockIdx.x * 8 + (threadIdx.x >> 5);
    int lane = threadIdx.x & 31;
    float* r = g_sc + (size_t)row * PP;

    float4 v[4];
#pragma unroll
    for (int i = 0; i < 4; i++)
        v[i] = *(const float4*)(r + (i*32 + lane)*4);

    float m = -1e30f;
#pragma unroll
    for (int i = 0; i < 4; i++) {
        m = fmaxf(m, fmaxf(fmaxf(v[i].x, v[i].y), fmaxf(v[i].z, v[i].w)));
    }
#pragma unroll
    for (int o = 16; o; o >>= 1) m = fmaxf(m, __shfl_xor_sync(0xffffffffu, m, o));

    float s = 0.f;
#pragma unroll
    for (int i = 0; i < 4; i++) {
        v[i].x = __expf(v[i].x - m);
        v[i].y = __expf(v[i].y - m);
        v[i].z = __expf(v[i].z - m);
        v[i].w = __expf(v[i].w - m);
        s += v[i].x + v[i].y + v[i].z + v[i].w;
    }
#pragma unroll
    for (int o = 16; o; o >>= 1) s += __shfl_xor_sync(0xffffffffu, s, o);

    float inv = 1.f / s;
#pragma unroll
    for (int i = 0; i < 4; i++) {
        v[i].x *= inv; v[i].y *= inv; v[i].z *= inv; v[i].w *= inv;
        *(float4*)(r + (i*32 + lane)*4) = v[i];
    }
}

// ---------------------------------------------------------------------------
// Kernel 5 (tensor, cp.async pipelined): out = attn @ v. M=512, K=512, N=256.
// ---------------------------------------------------------------------------
__global__ void __launch_bounds__(256, 2) av_tc(float* __restrict__ out) {
    extern __shared__ float smem[];
    float (*As)[128][36]  = (float (*)[128][36])smem;
    float (*Bs)[32][136]  = (float (*)[32][136])(smem + 2*128*36);

    int bc = blockIdx.z;
    const float* A = g_sc + (size_t)bc * PP * PP;   // ld = 512
    const float* V = g_v  + bc * PP * DD;           // ld = 256
    float*       O = out  + bc * PP * DD;

    int m0 = blockIdx.y * 128;
    int n0 = blockIdx.x * 128;
    int t  = threadIdx.x;
    int lane = t & 31, wid = t >> 5;
    int wm = wid >> 2, wn = wid & 3;
    int g = lane >> 2, tg = lane & 3;

    int arow = t >> 3, aq = (t & 7) * 4;
    int brow = t >> 5, bq4 = (t & 31) * 4;

    float acc[4][4][4] = {};

    {
        const int k0 = 0;
#pragma unroll
        for (int i = 0; i < 4; i++)
            cpa16(s2u(&As[0][arow + 32*i][aq]), &A[(size_t)(m0 + arow + 32*i)*PP + k0 + aq]);
#pragma unroll
        for (int i = 0; i < 4; i++)
            cpa16(s2u(&Bs[0][brow + 8*i][bq4]), &V[(k0 + brow + 8*i)*DD + n0 + bq4]);
        CP_COMMIT();
    }

    const int NCH = PP / 32;  // 16
    for (int ch = 0; ch < NCH; ch++) {
        if (ch + 1 < NCH) {
            const int k0 = (ch + 1) * 32;
            int nb = (ch + 1) & 1;
#pragma unroll
            for (int i = 0; i < 4; i++)
                cpa16(s2u(&As[nb][arow + 32*i][aq]), &A[(size_t)(m0 + arow + 32*i)*PP + k0 + aq]);
#pragma unroll
            for (int i = 0; i < 4; i++)
                cpa16(s2u(&Bs[nb][brow + 8*i][bq4]), &V[(k0 + brow + 8*i)*DD + n0 + bq4]);
            CP_COMMIT();
            CP_WAIT1();
        } else {
            CP_WAIT0();
        }
        __syncthreads();

        int cur = ch & 1;
        const float (*Ab)[36]  = As[cur];
        const float (*Bb)[136] = Bs[cur];
#pragma unroll
        for (int kt = 0; kt < 32; kt += 8) {
            uint32_t af[4][4], bf[4][2];
#pragma unroll
            for (int mt = 0; mt < 4; mt++) {
                int r = wm*64 + mt*16;
                af[mt][0] = f2tf(Ab[r+g   ][kt+tg]);
                af[mt][1] = f2tf(Ab[r+g+8 ][kt+tg]);
                af[mt][2] = f2tf(Ab[r+g   ][kt+tg+4]);
                af[mt][3] = f2tf(Ab[r+g+8 ][kt+tg+4]);
            }
#pragma unroll
            for (int nt = 0; nt < 4; nt++) {
                int cc2 = wn*32 + nt*8 + g;
                bf[nt][0] = f2tf(Bb[kt+tg  ][cc2]);
                bf[nt][1] = f2tf(Bb[kt+tg+4][cc2]);
            }
#pragma unroll
            for (int mt = 0; mt < 4; mt++)
#pragma unroll
                for (int nt = 0; nt < 4; nt++)
                    mma8(acc[mt][nt], af[mt], bf[nt]);
        }
        __syncthreads();
    }

#pragma unroll
    for (int mt = 0; mt < 4; mt++) {
#pragma unroll
        for (int nt = 0; nt < 4; nt++) {
            int row = m0 + wm*64 + mt*16 + g;
            int col = n0 + wn*32 + nt*8 + 2*tg;
            float* o = acc[mt][nt];
            *(float2*)&O[row*DD + col]     = make_float2(o[0], o[1]);
            *(float2*)&O[(row+8)*DD + col] = make_float2(o[2], o[3]);
        }
    }
}

// ---------------------------------------------------------------------------
extern "C" void kernel_launch(void* const* d_in, const int* in_sizes, int n_in,
                              void* d_out, int out_size) {
    (void)in_sizes; (void)n_in; (void)out_size;
    const float* query = (const float*)d_in[0];
    const float* aw    = (const float*)d_in[1];
    const float* wq    = (const float*)d_in[2];
    const float* wk    = (const float*)d_in[3];
    const float* wv    = (const float*)d_in[4];
    const float* bq    = (const float*)d_in[5];
    const float* bk    = (const float*)d_in[6];
    const float* bv    = (const float*)d_in[7];
    float* out = (float*)d_out;

    const int SM_PROJ   = 2*(128*36 + 32*136) * 4;   // 71680
    const int SM_SCORES = 2*(128*36 + 128*36) * 4;   // 73728
    const int SM_AV     = SM_PROJ;

    cudaFuncSetAttribute(proj_tc,   cudaFuncAttributeMaxDynamicSharedMemorySize, SM_SCORES);
    cudaFuncSetAttribute(scores_tc, cudaFuncAttributeMaxDynamicSharedMemorySize, SM_SCORES);
    cudaFuncSetAttribute(av_tc,     cudaFuncAttributeMaxDynamicSharedMemorySize, SM_SCORES);

    int n_ctx = BB*PP*DD;
    ctx_kernel<<<(n_ctx + 255)/256, 256>>>(query, aw);
    proj_tc<<<dim3(DD/128, PP/128, 3*BB*CC), 256, SM_PROJ>>>(query, wq, wk, wv, bq, bk, bv);
    scores_tc<<<dim3(PP/128, PP/128, BB*CC), 256, SM_SCORES>>>();
    softmax_warp<<<BB*CC*PP/8, 256>>>();
    av_tc<<<dim3(DD/128, PP/128, BB*CC), 256, SM_AV>>>(out);
}

// round 10
// speedup vs baseline: 5.7308x; 1.5875x over previous
#include <cuda_runtime.h>
#include <cuda_bf16.h>
#include <cstdint>

#define BB 16
#define CC 16
#define PP 512
#define DD 256

typedef __nv_bfloat16  bf16;
typedef __nv_bfloat162 bf162;

// Scratch (allocation-free rule: __device__ globals)
__device__ bf16  g_qb  [BB*CC*PP*DD];   // 67 MB  bf16(query)
__device__ bf16  g_ctxb[BB*CC*PP*DD];   // 67 MB  bf16(context)
__device__ bf16  g_wt  [3*CC*DD*DD];    // 6.3 MB transposed weights [e][d]
__device__ bf16  g_q   [BB*CC*PP*DD];   // 67 MB
__device__ bf16  g_k   [BB*CC*PP*DD];   // 67 MB
__device__ bf16  g_v   [BB*CC*PP*DD];   // 67 MB
__device__ bf16  g_vt  [BB*CC*PP*DD];   // 67 MB  V^T [e][q]
__device__ float g_sc  [BB*CC*PP*PP];   // 268 MB scores fp32
__device__ bf16  g_pb  [BB*CC*PP*PP];   // 134 MB probs bf16

// ---------------------------------------------------------------------------
// helpers
// ---------------------------------------------------------------------------
__device__ __forceinline__ void mma16(float* c, const uint32_t* a, const uint32_t* b) {
    asm volatile(
        "mma.sync.aligned.m16n8k16.row.col.f32.bf16.bf16.f32 "
        "{%0,%1,%2,%3}, {%4,%5,%6,%7}, {%8,%9}, {%0,%1,%2,%3};"
        : "+f"(c[0]), "+f"(c[1]), "+f"(c[2]), "+f"(c[3])
        : "r"(a[0]), "r"(a[1]), "r"(a[2]), "r"(a[3]), "r"(b[0]), "r"(b[1]));
}

__device__ __forceinline__ void cpa16(uint32_t dst, const void* src) {
    asm volatile("cp.async.cg.shared.global [%0], [%1], 16;" :: "r"(dst), "l"(src));
}
#define CP_COMMIT() asm volatile("cp.async.commit_group;")
#define CP_WAIT0()  asm volatile("cp.async.wait_group 0;")
#define CP_WAIT1()  asm volatile("cp.async.wait_group 1;")

__device__ __forceinline__ uint32_t s2u(const void* p) {
    return (uint32_t)__cvta_generic_to_shared(p);
}

__device__ __forceinline__ uint32_t pack_bf(float lo, float hi) {
    bf162 h = __float22bfloat162_rn(make_float2(lo, hi));
    return *(uint32_t*)&h;
}

// ---------------------------------------------------------------------------
// Shared bf16 GEMM mainloop: C[128,128] tile, Kc=64, double-buffered cp.async.
// A: [m][k] k-contig (lda), B: [n][k] k-contig (ldb). 256 threads, 8 warps 64x32.
// smem rows padded to 72 bf16 (144B = 36 words, 36 % 32 == 4 -> conflict-free).
// ---------------------------------------------------------------------------
template<int KTOT>
__device__ __forceinline__ void gemm_bf16(
    const bf16* __restrict__ A, int lda,
    const bf16* __restrict__ B, int ldb,
    int m0, int n0, char* smemraw, float acc[4][4][4])
{
    bf16 (*As)[128][72] = (bf16 (*)[128][72])smemraw;
    bf16 (*Bs)[128][72] = (bf16 (*)[128][72])(smemraw + 2*128*72*2);

    int t = threadIdx.x;
    int lane = t & 31, wid = t >> 5;
    int wm = wid >> 2, wn = wid & 3;
    int g = lane >> 2, tg = lane & 3;

    int rA = t >> 3, c8 = (t & 7) * 8;   // 128 rows x 64 bf16 per tile, 16B chunks

    // prologue: chunk 0 -> buf 0
#pragma unroll
    for (int i = 0; i < 4; i++)
        cpa16(s2u(&As[0][rA + 32*i][c8]), A + (size_t)(m0 + rA + 32*i)*lda + c8);
#pragma unroll
    for (int i = 0; i < 4; i++)
        cpa16(s2u(&Bs[0][rA + 32*i][c8]), B + (size_t)(n0 + rA + 32*i)*ldb + c8);
    CP_COMMIT();

    const int NCH = KTOT / 64;
    for (int ch = 0; ch < NCH; ch++) {
        if (ch + 1 < NCH) {
            int k0 = (ch + 1) * 64;
            int nb = (ch + 1) & 1;
#pragma unroll
            for (int i = 0; i < 4; i++)
                cpa16(s2u(&As[nb][rA + 32*i][c8]), A + (size_t)(m0 + rA + 32*i)*lda + k0 + c8);
#pragma unroll
            for (int i = 0; i < 4; i++)
                cpa16(s2u(&Bs[nb][rA + 32*i][c8]), B + (size_t)(n0 + rA + 32*i)*ldb + k0 + c8);
            CP_COMMIT();
            CP_WAIT1();
        } else {
            CP_WAIT0();
        }
        __syncthreads();

        int cur = ch & 1;
#pragma unroll
        for (int kt = 0; kt < 64; kt += 16) {
            uint32_t af[4][4], bfr[4][2];
#pragma unroll
            for (int mt = 0; mt < 4; mt++) {
                int r = wm*64 + mt*16;
                af[mt][0] = *(const uint32_t*)&As[cur][r+g  ][kt + 2*tg];
                af[mt][1] = *(const uint32_t*)&As[cur][r+g+8][kt + 2*tg];
                af[mt][2] = *(const uint32_t*)&As[cur][r+g  ][kt + 2*tg + 8];
                af[mt][3] = *(const uint32_t*)&As[cur][r+g+8][kt + 2*tg + 8];
            }
#pragma unroll
            for (int nt = 0; nt < 4; nt++) {
                int n = wn*32 + nt*8 + g;
                bfr[nt][0] = *(const uint32_t*)&Bs[cur][n][kt + 2*tg];
                bfr[nt][1] = *(const uint32_t*)&Bs[cur][n][kt + 2*tg + 8];
            }
#pragma unroll
            for (int mt = 0; mt < 4; mt++)
#pragma unroll
                for (int nt = 0; nt < 4; nt++)
                    mma16(acc[mt][nt], af[mt], bfr[nt]);
        }
        __syncthreads();
    }
}

static const int GEMM_SMEM = 2*128*72*2 * 2;   // 73728 B

// ---------------------------------------------------------------------------
// Kernel 0: weight transpose+convert: W[c][d][e] fp32 -> g_wt[type][c][e][d] bf16
// ---------------------------------------------------------------------------
__global__ void wt_kernel(const float* __restrict__ wq,
                          const float* __restrict__ wk,
                          const float* __restrict__ wv) {
    __shared__ float s[32][33];
    int z = blockIdx.z;
    int type = z / CC, c = z % CC;
    const float* W = (type == 0 ? wq : (type == 1 ? wk : wv)) + (size_t)c*DD*DD;
    bf16* O = g_wt + (size_t)(type*CC + c)*DD*DD;
    int d0 = blockIdx.y * 32, e0 = blockIdx.x * 32;
    int tx = threadIdx.x, ty = threadIdx.y;
#pragma unroll
    for (int j = 0; j < 4; j++)
        s[ty + 8*j][tx] = W[(d0 + ty + 8*j)*DD + e0 + tx];
    __syncthreads();
#pragma unroll
    for (int j = 0; j < 4; j++)
        O[(e0 + ty + 8*j)*DD + d0 + tx] = __float2bfloat16(s[tx][ty + 8*j]);
}

// ---------------------------------------------------------------------------
// Kernel 1: context + bf16 conversions of query and context
// ---------------------------------------------------------------------------
__global__ void ctx_kernel(const float* __restrict__ query,
                           const float* __restrict__ aw) {
    int idx = blockIdx.x * blockDim.x + threadIdx.x;  // over B*P*D
    if (idx >= BB*PP*DD) return;
    int d = idx % DD;
    int p = (idx / DD) % PP;
    int b = idx / (PP*DD);

    float vals[CC];
    float sum = 0.f;
#pragma unroll
    for (int c = 0; c < CC; c++) {
        int ii = ((b*CC + c)*PP + p)*DD + d;
        float qv = query[ii];
        float v  = aw[(c*PP + p)*DD + d] * qv;
        vals[c] = v;
        sum += v;
        g_qb[ii] = __float2bfloat16(qv);
    }
#pragma unroll
    for (int c = 0; c < CC; c++) {
        g_ctxb[((b*CC + c)*PP + p)*DD + d] = __float2bfloat16(sum - vals[c]);
    }
}

// ---------------------------------------------------------------------------
// Kernel 2: fused q/k/v projections (bf16 MMA). out = relu(X@W+b) [*1/16 q]
// ---------------------------------------------------------------------------
__global__ void __launch_bounds__(256, 2) proj_bf(const float* __restrict__ bq,
                                                  const float* __restrict__ bk,
                                                  const float* __restrict__ bv) {
    extern __shared__ char smem[];
    int z    = blockIdx.z;
    int type = z / (BB*CC);
    int bc   = z % (BB*CC);
    int c    = bc % CC;

    const bf16* A    = (type == 0 ? g_qb : g_ctxb) + (size_t)bc * PP * DD;
    const bf16* Bw   = g_wt + (size_t)(type*CC + c) * DD * DD;
    const float* bias = (type == 0 ? bq : (type == 1 ? bk : bv)) + c * DD;
    bf16*       out  = (type == 0 ? g_q : (type == 1 ? g_k : g_v)) + (size_t)bc * PP * DD;

    int m0 = blockIdx.y * 128;
    int n0 = blockIdx.x * 128;

    float acc[4][4][4] = {};
    gemm_bf16<DD>(A, DD, Bw, DD, m0, n0, smem, acc);

    int t = threadIdx.x;
    int lane = t & 31, wid = t >> 5;
    int wm = wid >> 2, wn = wid & 3;
    int g = lane >> 2, tg = lane & 3;
    float scale = (type == 0) ? 0.0625f : 1.0f;
#pragma unroll
    for (int mt = 0; mt < 4; mt++) {
#pragma unroll
        for (int nt = 0; nt < 4; nt++) {
            int row = m0 + wm*64 + mt*16 + g;
            int col = n0 + wn*32 + nt*8 + 2*tg;
            float b0v = bias[col], b1v = bias[col+1];
            float* o = acc[mt][nt];
            *(uint32_t*)&out[(size_t)row*DD + col] =
                pack_bf(fmaxf(o[0]+b0v, 0.f)*scale, fmaxf(o[1]+b1v, 0.f)*scale);
            *(uint32_t*)&out[(size_t)(row+8)*DD + col] =
                pack_bf(fmaxf(o[2]+b0v, 0.f)*scale, fmaxf(o[3]+b1v, 0.f)*scale);
        }
    }
}

// ---------------------------------------------------------------------------
// Kernel 3: scores = q @ k^T (bf16 in, fp32 out)
// ---------------------------------------------------------------------------
__global__ void __launch_bounds__(256, 2) scores_bf() {
    extern __shared__ char smem[];
    int bc = blockIdx.z;
    const bf16* Q = g_q + (size_t)bc * PP * DD;
    const bf16* K = g_k + (size_t)bc * PP * DD;
    float*      S = g_sc + (size_t)bc * PP * PP;

    int m0 = blockIdx.y * 128;
    int n0 = blockIdx.x * 128;

    float acc[4][4][4] = {};
    gemm_bf16<DD>(Q, DD, K, DD, m0, n0, smem, acc);

    int t = threadIdx.x;
    int lane = t & 31, wid = t >> 5;
    int wm = wid >> 2, wn = wid & 3;
    int g = lane >> 2, tg = lane & 3;
#pragma unroll
    for (int mt = 0; mt < 4; mt++) {
#pragma unroll
        for (int nt = 0; nt < 4; nt++) {
            int row = m0 + wm*64 + mt*16 + g;
            int col = n0 + wn*32 + nt*8 + 2*tg;
            float* o = acc[mt][nt];
            *(float2*)&S[(size_t)row*PP + col]     = make_float2(o[0], o[1]);
            *(float2*)&S[(size_t)(row+8)*PP + col] = make_float2(o[2], o[3]);
        }
    }
}

// ---------------------------------------------------------------------------
// Kernel 4: softmax, one warp per 512 row; fp32 in, bf16 probs out.
// ---------------------------------------------------------------------------
__global__ void softmax_warp() {
    int row  = blockIdx.x * 8 + (threadIdx.x >> 5);
    int lane = threadIdx.x & 31;
    const float* r = g_sc + (size_t)row * PP;
    bf16* pb = g_pb + (size_t)row * PP;

    float4 v[4];
#pragma unroll
    for (int i = 0; i < 4; i++)
        v[i] = *(const float4*)(r + (i*32 + lane)*4);

    float m = -1e30f;
#pragma unroll
    for (int i = 0; i < 4; i++)
        m = fmaxf(m, fmaxf(fmaxf(v[i].x, v[i].y), fmaxf(v[i].z, v[i].w)));
#pragma unroll
    for (int o = 16; o; o >>= 1) m = fmaxf(m, __shfl_xor_sync(0xffffffffu, m, o));

    float s = 0.f;
#pragma unroll
    for (int i = 0; i < 4; i++) {
        v[i].x = __expf(v[i].x - m);
        v[i].y = __expf(v[i].y - m);
        v[i].z = __expf(v[i].z - m);
        v[i].w = __expf(v[i].w - m);
        s += v[i].x + v[i].y + v[i].z + v[i].w;
    }
#pragma unroll
    for (int o = 16; o; o >>= 1) s += __shfl_xor_sync(0xffffffffu, s, o);

    float inv = 1.f / s;
#pragma unroll
    for (int i = 0; i < 4; i++) {
        uint2 u;
        u.x = pack_bf(v[i].x * inv, v[i].y * inv);
        u.y = pack_bf(v[i].z * inv, v[i].w * inv);
        *(uint2*)(pb + (i*32 + lane)*4) = u;
    }
}

// ---------------------------------------------------------------------------
// Kernel 5: V transpose: g_v [p][e] bf16 -> g_vt [e][p] bf16 per (b,c)
// ---------------------------------------------------------------------------
__global__ void vt_kernel() {
    __shared__ bf16 s[32][34];
    int bc = blockIdx.z;
    const bf16* V = g_v  + (size_t)bc * PP * DD;
    bf16*       O = g_vt + (size_t)bc * DD * PP;
    int p0 = blockIdx.y * 32, e0 = blockIdx.x * 32;
    int tx = threadIdx.x, ty = threadIdx.y;
#pragma unroll
    for (int j = 0; j < 4; j++)
        s[ty + 8*j][tx] = V[(size_t)(p0 + ty + 8*j)*DD + e0 + tx];
    __syncthreads();
#pragma unroll
    for (int j = 0; j < 4; j++)
        O[(size_t)(e0 + ty + 8*j)*PP + p0 + tx] = s[tx][ty + 8*j];
}

// ---------------------------------------------------------------------------
// Kernel 6: out = probs @ v (bf16 in, fp32 out). M=512, K=512, N=256.
// ---------------------------------------------------------------------------
__global__ void __launch_bounds__(256, 2) av_bf(float* __restrict__ out) {
    extern __shared__ char smem[];
    int bc = blockIdx.z;
    const bf16* A = g_pb + (size_t)bc * PP * PP;   // [p][q], ld PP
    const bf16* B = g_vt + (size_t)bc * DD * PP;   // [e][q], ld PP
    float*      O = out  + (size_t)bc * PP * DD;

    int m0 = blockIdx.y * 128;
    int n0 = blockIdx.x * 128;

    float acc[4][4][4] = {};
    gemm_bf16<PP>(A, PP, B, PP, m0, n0, smem, acc);

    int t = threadIdx.x;
    int lane = t & 31, wid = t >> 5;
    int wm = wid >> 2, wn = wid & 3;
    int g = lane >> 2, tg = lane & 3;
#pragma unroll
    for (int mt = 0; mt < 4; mt++) {
#pragma unroll
        for (int nt = 0; nt < 4; nt++) {
            int row = m0 + wm*64 + mt*16 + g;
            int col = n0 + wn*32 + nt*8 + 2*tg;
            float* o = acc[mt][nt];
            *(float2*)&O[(size_t)row*DD + col]     = make_float2(o[0], o[1]);
            *(float2*)&O[(size_t)(row+8)*DD + col] = make_float2(o[2], o[3]);
        }
    }
}

// ---------------------------------------------------------------------------
extern "C" void kernel_launch(void* const* d_in, const int* in_sizes, int n_in,
                              void* d_out, int out_size) {
    (void)in_sizes; (void)n_in; (void)out_size;
    const float* query = (const float*)d_in[0];
    const float* aw    = (const float*)d_in[1];
    const float* wq    = (const float*)d_in[2];
    const float* wk    = (const float*)d_in[3];
    const float* wv    = (const float*)d_in[4];
    const float* bq    = (const float*)d_in[5];
    const float* bk    = (const float*)d_in[6];
    const float* bv    = (const float*)d_in[7];
    float* out = (float*)d_out;

    cudaFuncSetAttribute(proj_bf,   cudaFuncAttributeMaxDynamicSharedMemorySize, GEMM_SMEM);
    cudaFuncSetAttribute(scores_bf, cudaFuncAttributeMaxDynamicSharedMemorySize, GEMM_SMEM);
    cudaFuncSetAttribute(av_bf,     cudaFuncAttributeMaxDynamicSharedMemorySize, GEMM_SMEM);

    wt_kernel<<<dim3(8, 8, 3*CC), dim3(32, 8)>>>(wq, wk, wv);
    int n_ctx = BB*PP*DD;
    ctx_kernel<<<(n_ctx + 255)/256, 256>>>(query, aw);
    proj_bf<<<dim3(DD/128, PP/128, 3*BB*CC), 256, GEMM_SMEM>>>(bq, bk, bv);
    scores_bf<<<dim3(PP/128, PP/128, BB*CC), 256, GEMM_SMEM>>>();
    softmax_warp<<<BB*CC*PP/8, 256>>>();
    vt_kernel<<<dim3(DD/32, PP/32, BB*CC), dim3(32, 8)>>>();
    av_bf<<<dim3(DD/128, PP/128, BB*CC), 256, GEMM_SMEM>>>(out);
}